// round 13
// baseline (speedup 1.0000x reference)
#include <cuda_runtime.h>
#include <cstdint>

// ============================================================================
// SparseQuanvLayer: 4-qubit random circuit over strided 2x2x2 patches.
//
// z_w = h^T M_w k with h = g0 (x) g1, k = g2 (x) g3, g = (1, cos pi*phi,
// sin pi*phi); M_w are 4x81 coefficients derived from the circuit unitary.
//
// R12 -> R13 (quanv was L1/LDS-bound at 57%, issue 33%):
//  * Coefficient rows padded to stride 10 (16B aligned): 4x LDS.128 + 1x
//    LDS.64 per 9-wide row instead of 9x LDS.64  (324 -> 180 LDS/warp).
//  * Even/odd dual-chain accumulation + K0=1/H0=1 shortcuts: ~2x shorter
//    FFMA2 dependency chains at equal instruction count.
//  * Setup kernel 128 threads (cheaper barriers).
// ============================================================================

// ---------------- numpy RNG replication (host-side) -------------------------

struct Pcg {
    unsigned __int128 state, inc;
    int has32;
    unsigned int buf32;
};

__host__ __device__ __forceinline__ void pcg_step(Pcg& g) {
    const unsigned __int128 mult =
        (((unsigned __int128)0x2360ed051fc65da4ULL) << 64) | 0x4385df649fccf645ULL;
    g.state = g.state * mult + g.inc;
}

__host__ __device__ __forceinline__ unsigned long long pcg_next64(Pcg& g) {
    pcg_step(g);
    unsigned long long hi = (unsigned long long)(g.state >> 64);
    unsigned long long lo = (unsigned long long)g.state;
    unsigned int rot = (unsigned int)(g.state >> 122);
    unsigned long long x = hi ^ lo;
    return (x >> rot) | (x << ((64u - rot) & 63u));
}

__host__ __device__ __forceinline__ unsigned int pcg_next32(Pcg& g) {
    if (g.has32) { g.has32 = 0; return g.buf32; }
    unsigned long long v = pcg_next64(g);
    g.has32 = 1;
    g.buf32 = (unsigned int)(v >> 32);
    return (unsigned int)v;
}

__host__ __device__ __forceinline__ double rng_double(Pcg& g) {
    return (double)(pcg_next64(g) >> 11) * (1.0 / 9007199254740992.0);
}

// Generator.integers -> buffered_bounded_lemire_uint32 (rng_excl = max+1)
__host__ __device__ unsigned int lemire32(Pcg& g, unsigned int rng_excl) {
    unsigned long long m = (unsigned long long)pcg_next32(g) * (unsigned long long)rng_excl;
    unsigned int leftover = (unsigned int)m;
    if (leftover < rng_excl) {
        unsigned int threshold = (unsigned int)(0u - rng_excl) % rng_excl;
        while (leftover < threshold) {
            m = (unsigned long long)pcg_next32(g) * (unsigned long long)rng_excl;
            leftover = (unsigned int)m;
        }
    }
    return (unsigned int)(m >> 32);
}

// Generator.shuffle -> _shuffle_raw -> random_interval (masked rejection)
__host__ __device__ unsigned int rand_interval(Pcg& g, unsigned int mx) {
    if (mx == 0) return 0;
    unsigned int mask = mx;
    mask |= mask >> 1; mask |= mask >> 2; mask |= mask >> 4;
    mask |= mask >> 8; mask |= mask >> 16;
    unsigned int v;
    do { v = pcg_next32(g) & mask; } while (v > mx);
    return v;
}

__host__ __device__ unsigned int ss_hashmix(unsigned int value, unsigned int& hc) {
    value ^= hc;
    hc *= 0x931e8875u;   // MULT_A
    value *= hc;
    value ^= value >> 16;
    return value;
}

// SeedSequence.mix: x*MIX_MULT_L - y*MIX_MULT_R, then xor-shift
__host__ __device__ unsigned int ss_mix(unsigned int x, unsigned int y) {
    unsigned int r = x * 0xca01f9ddu;
    r -= y * 0x4973f715u;
    r ^= r >> 16;
    return r;
}

__host__ __device__ void pcg_seed42(Pcg& g) {
    unsigned int pool[4];
    unsigned int hc = 0x43b0d7e5u;  // INIT_A
    pool[0] = ss_hashmix(42u, hc);
    pool[1] = ss_hashmix(0u, hc);
    pool[2] = ss_hashmix(0u, hc);
    pool[3] = ss_hashmix(0u, hc);
    for (int src = 0; src < 4; src++)
        for (int dst = 0; dst < 4; dst++)
            if (src != dst)
                pool[dst] = ss_mix(pool[dst], ss_hashmix(pool[src], hc));
    unsigned int hb = 0x8b51f9ddu;  // INIT_B
    unsigned long long val[4];
    for (int i = 0; i < 4; i++) {
        unsigned int w32[2];
        for (int h = 0; h < 2; h++) {
            unsigned int dv = pool[(2 * i + h) & 3];
            dv ^= hb;
            hb *= 0x58f38dedu;  // MULT_B
            dv *= hb;
            dv ^= dv >> 16;
            w32[h] = dv;
        }
        val[i] = (unsigned long long)w32[0] | ((unsigned long long)w32[1] << 32);
    }
    unsigned __int128 initstate = (((unsigned __int128)val[0]) << 64) | val[1];
    unsigned __int128 initseq   = (((unsigned __int128)val[2]) << 64) | val[3];
    g.state = 0;
    g.inc = (initseq << 1) | 1;
    pcg_step(g);
    g.state += initstate;
    pcg_step(g);
    g.has32 = 0;
    g.buf32 = 0;
}

// ---------------- op list (computed on HOST, passed by value) ---------------

#define MAXOPS 64

struct OpsArg {
    int n;
    signed char type[MAXOPS], a[MAXOPS], b[MAXOPS], p[MAXOPS];
};

static void build_ops_host(OpsArg& o) {
    Pcg g;
    pcg_seed42(g);
    int i = 0;
    o.n = 0;
    while (i < 4 && o.n < MAXOPS) {
        if (rng_double(g) > 0.3) {
            int kind = (int)lemire32(g, 3u);   // integers(0,3)
            int w    = (int)lemire32(g, 4u);   // integers(0,4)
            o.type[o.n] = 0; o.a[o.n] = (signed char)kind;
            o.b[o.n] = (signed char)w; o.p[o.n] = (signed char)i;
            o.n++; i++;
        } else {
            int arr[4] = {0, 1, 2, 3};
            for (int ii = 3; ii >= 1; ii--) {
                int jj = (int)rand_interval(g, (unsigned)ii);
                int tmp = arr[ii]; arr[ii] = arr[jj]; arr[jj] = tmp;
            }
            o.type[o.n] = 1; o.a[o.n] = (signed char)arr[0];
            o.b[o.n] = (signed char)arr[1]; o.p[o.n] = 0;
            o.n++;
        }
    }
}

// ---------------- coefficients: padded stride-10 rows, duplicated pairs -----

// d_M2[(w*9 + r)*10 + c], c in 0..8; slot 9 is padding. Each row 16B-aligned.
__device__ unsigned long long d_M2[360];

// ---------------- setup kernel: fp32, one 128-thread block ------------------

__global__ void __launch_bounds__(128) setup_kernel(const float* __restrict__ rp,
                                                    OpsArg ops) {
    __shared__ float Ur[16][16], Ui[16][16];
    __shared__ float Q[4][16][16];
    int t = threadIdx.x;

    for (int e = t; e < 256; e += 128) {
        Ur[e >> 4][e & 15] = ((e >> 4) == (e & 15)) ? 1.0f : 0.0f;
        Ui[e >> 4][e & 15] = 0.0f;
    }
    __syncthreads();

    for (int o = 0; o < ops.n; o++) {
        if (ops.type[o] == 0) {
            float th = rp[(int)ops.p[o]];
            float ch, sh;
            sincosf(0.5f * th, &sh, &ch);
            int kind = ops.a[o];
            float u00r = ch, u00i = 0, u01r = 0, u01i = 0;
            float u10r = 0,  u10i = 0, u11r = ch, u11i = 0;
            if (kind == 0)      { u01i = -sh; u10i = -sh; }           // RX
            else if (kind == 1) { u01r = -sh; u10r =  sh; }           // RY
            else                { u00i = -sh; u11i =  sh; }           // RZ
            int bit = 1 << (3 - (int)ops.b[o]);
            {
                int pair = t >> 4, col = t & 15;   // 128 threads = 8 pairs x 16 cols
                int low = pair & (bit - 1);
                int high = (pair ^ low) << 1;
                int s0 = high | low, s1 = s0 | bit;
                float ar = Ur[s0][col], ai = Ui[s0][col];
                float br = Ur[s1][col], bi = Ui[s1][col];
                Ur[s0][col] = u00r * ar - u00i * ai + u01r * br - u01i * bi;
                Ui[s0][col] = u00r * ai + u00i * ar + u01r * bi + u01i * br;
                Ur[s1][col] = u10r * ar - u10i * ai + u11r * br - u11i * bi;
                Ui[s1][col] = u10r * ai + u10i * ar + u11r * bi + u11i * br;
            }
        } else {
            int cb = 1 << (3 - (int)ops.a[o]);
            int tb = 1 << (3 - (int)ops.b[o]);
            if (t < 64) {
                int pi = t >> 4, col = t & 15;
                int s0 = cb, rr = pi;
                for (int bp = 0; bp < 4; bp++) {
                    int bb = 1 << bp;
                    if (bb == cb || bb == tb) continue;
                    if (rr & 1) s0 |= bb;
                    rr >>= 1;
                }
                int s1 = s0 | tb;
                float xr = Ur[s0][col], xi = Ui[s0][col];
                Ur[s0][col] = Ur[s1][col]; Ui[s0][col] = Ui[s1][col];
                Ur[s1][col] = xr;          Ui[s1][col] = xi;
            }
        }
        __syncthreads();
    }

    // Q_w[a][b] = sum_s sign_w(s) * (Ur[s][a]Ur[s][b] + Ui[s][a]Ui[s][b])
    for (int task = t; task < 1024; task += 128) {
        int w = task >> 8, a = (task >> 4) & 15, b = task & 15;
        int bit = 1 << (3 - w);
        float q = 0;
        for (int s = 0; s < 16; s++) {
            float v = Ur[s][a] * Ur[s][b] + Ui[s][a] * Ui[s][b];
            q += (s & bit) ? -v : v;
        }
        Q[w][a][b] = q;
    }
    __syncthreads();

    // Basis change {cos^2, sin^2, cs} -> {1, C, S}; duplicated pairs, padded rows.
    for (int task = t; task < 324; task += 128) {
        int w = task / 81, m = task % 81;
        int mm[4] = { m / 27, (m / 9) % 3, (m / 3) % 3, m % 3 };
        float acc = 0;
        for (int c = 0; c < 16; c++) {
            int a = 0, b = 0;
            float sgn = 1.0f;
            #pragma unroll
            for (int k = 0; k < 4; k++) {
                int sel = (c >> k) & 1;
                int mk = mm[k];
                int i_, j_;
                if (mk == 2) { i_ = sel; j_ = 1 - sel; }
                else         { i_ = sel; j_ = sel; if (mk == 1 && sel == 1) sgn = -sgn; }
                int bitp = 3 - k;
                a |= i_ << bitp;
                b |= j_ << bitp;
            }
            acc += sgn * Q[w][a][b];
        }
        unsigned int bits = __float_as_uint(acc * 0.0625f);
        int r = (m / 9), c = m % 9;
        d_M2[(w * 9 + r) * 10 + c] = ((unsigned long long)bits << 32) | bits;
    }
}

// ---------------- packed f32x2 helpers --------------------------------------

__device__ __forceinline__ unsigned long long fma2(unsigned long long a,
                                                   unsigned long long b,
                                                   unsigned long long c) {
    unsigned long long d;
    asm("fma.rn.f32x2 %0, %1, %2, %3;" : "=l"(d) : "l"(a), "l"(b), "l"(c));
    return d;
}

__device__ __forceinline__ unsigned long long mul2(unsigned long long a,
                                                   unsigned long long b) {
    unsigned long long d;
    asm("mul.rn.f32x2 %0, %1, %2;" : "=l"(d) : "l"(a), "l"(b));
    return d;
}

__device__ __forceinline__ unsigned long long add2(unsigned long long a,
                                                   unsigned long long b) {
    unsigned long long d;
    asm("add.rn.f32x2 %0, %1, %2;" : "=l"(d) : "l"(a), "l"(b));
    return d;
}

__device__ __forceinline__ unsigned long long pack2(float lo, float hi) {
    unsigned long long r;
    asm("mov.b64 %0, {%1, %2};" : "=l"(r) : "f"(lo), "f"(hi));
    return r;
}

__device__ __forceinline__ void unpack2(unsigned long long v, float& lo, float& hi) {
    asm("mov.b64 {%0, %1}, %2;" : "=f"(lo), "=f"(hi) : "l"(v));
}

// ---------------- main kernel: 2 elements/thread, FFMA2 + LDS.128 -----------

__global__ void __launch_bounds__(256) quanv_kernel(const float* __restrict__ x,
                                                    float* __restrict__ out) {
    __shared__ __align__(16) unsigned long long MsD[360];
    for (int u = threadIdx.x; u < 360; u += 256) MsD[u] = d_M2[u];
    __syncthreads();

    int t = blockIdx.x * 256 + threadIdx.x;          // 0 .. 262143
    int n0 = t * 2;                                   // even element index
    int kk = n0 & 31, j = (n0 >> 5) & 31, i = (n0 >> 10) & 31, b = n0 >> 15;
    const float* xb = x + b * 262144;
    int base = i * 8192 + j * 128 + kk * 2;           // multiple of 4 (kk even)

    // Pair of patches: elem0 at base, elem1 at base+2; all float4 16B-aligned.
    float4 A = *reinterpret_cast<const float4*>(xb + base);          // p0: .x/.z
    float4 B = *reinterpret_cast<const float4*>(xb + base + 4160);   // p1: .x/.z
    float4 C = *reinterpret_cast<const float4*>(xb + base + 64);     // p2: .y/.w
    float4 D = *reinterpret_cast<const float4*>(xb + base + 4096);   // p3: .y/.w

    const float PI = 3.14159265358979323846f;
    float c0a, s0a, c1a, s1a, c2a, s2a, c3a, s3a;     // element 0
    float c0b, s0b, c1b, s1b, c2b, s2b, c3b, s3b;     // element 1
    __sincosf(PI * A.x, &s0a, &c0a);
    __sincosf(PI * B.x, &s1a, &c1a);
    __sincosf(PI * C.y, &s2a, &c2a);
    __sincosf(PI * D.y, &s3a, &c3a);
    __sincosf(PI * A.z, &s0b, &c0b);
    __sincosf(PI * B.z, &s1b, &c1b);
    __sincosf(PI * C.w, &s2b, &c2b);
    __sincosf(PI * D.w, &s3b, &c3b);

    // h = g0 (x) g1, k = g2 (x) g3 with g = (1, C, S); packed (elem0, elem1).
    // Index 0 of each is the constant 1 -> handled implicitly (no register).
    unsigned long long H1 = pack2(c1a, c1b);
    unsigned long long H2 = pack2(s1a, s1b);
    unsigned long long H3 = pack2(c0a, c0b);
    unsigned long long H4 = pack2(c0a * c1a, c0b * c1b);
    unsigned long long H5 = pack2(c0a * s1a, c0b * s1b);
    unsigned long long H6 = pack2(s0a, s0b);
    unsigned long long H7 = pack2(s0a * c1a, s0b * c1b);
    unsigned long long H8 = pack2(s0a * s1a, s0b * s1b);
    unsigned long long K1 = pack2(c3a, c3b);
    unsigned long long K2 = pack2(s3a, s3b);
    unsigned long long K3 = pack2(c2a, c2b);
    unsigned long long K4 = pack2(c2a * c3a, c2b * c3b);
    unsigned long long K5 = pack2(c2a * s3a, c2b * s3b);
    unsigned long long K6 = pack2(s2a, s2b);
    unsigned long long K7 = pack2(s2a * c3a, s2b * c3b);
    unsigned long long K8 = pack2(s2a * s3a, s2b * s3b);
    unsigned long long Hs[9] = {0ULL, H1, H2, H3, H4, H5, H6, H7, H8};

    float4 r0, r1;
    float* r0p = &r0.x;
    float* r1p = &r1.x;
    #pragma unroll
    for (int w = 0; w < 4; w++) {
        unsigned long long acc0 = 0ULL, acc1 = 0ULL;
        #pragma unroll
        for (int r = 0; r < 9; r++) {
            const unsigned long long* row = &MsD[(w * 9 + r) * 10];
            ulonglong2 P0 = *reinterpret_cast<const ulonglong2*>(row);      // c0,c1
            ulonglong2 P1 = *reinterpret_cast<const ulonglong2*>(row + 2);  // c2,c3
            ulonglong2 P2 = *reinterpret_cast<const ulonglong2*>(row + 4);  // c4,c5
            ulonglong2 P3 = *reinterpret_cast<const ulonglong2*>(row + 6);  // c6,c7
            unsigned long long m8 = row[8];
            // even/odd split: u0 = c0 + c2*K2 + c4*K4 + c6*K6 + c8*K8 (c0*1 free)
            //                 u1 = c1*K1 + c3*K3 + c5*K5 + c7*K7
            unsigned long long u0 = fma2(P1.x, K2, P0.x);
            unsigned long long u1 = mul2(P0.y, K1);
            u0 = fma2(P2.x, K4, u0);
            u1 = fma2(P1.y, K3, u1);
            u0 = fma2(P3.x, K6, u0);
            u1 = fma2(P2.y, K5, u1);
            u0 = fma2(m8, K8, u0);
            u1 = fma2(P3.y, K7, u1);
            if (r == 0) { acc0 = u0; acc1 = u1; }      // H[0] = 1
            else {
                acc0 = fma2(Hs[r], u0, acc0);
                acc1 = fma2(Hs[r], u1, acc1);
            }
        }
        unpack2(add2(acc0, acc1), r0p[w], r1p[w]);
    }
    float4* o4 = reinterpret_cast<float4*>(out);
    o4[n0]     = r0;
    o4[n0 + 1] = r1;
}

// ---------------- launch ----------------------------------------------------

extern "C" void kernel_launch(void* const* d_in, const int* in_sizes, int n_in,
                              void* d_out, int out_size) {
    const float* x;
    const float* rp;
    if (n_in >= 2 && in_sizes[0] == 4) {
        rp = (const float*)d_in[0];
        x  = (const float*)d_in[1];
    } else {
        x  = (const float*)d_in[0];
        rp = (const float*)d_in[1];
    }
    OpsArg ops;
    build_ops_host(ops);                 // deterministic per call (seed 42)
    setup_kernel<<<1, 128>>>(rp, ops);
    quanv_kernel<<<1024, 256>>>(x, (float*)d_out);
}